// round 3
// baseline (speedup 1.0000x reference)
#include <cuda_runtime.h>

#define DEVINL __device__ __forceinline__

constexpr int B = 64, T = 256, W = 20, NP = 6, NT = 12, CC = 32, FD = 8, PROJ = 64;
constexpr int NG = 4 * PROJ;            // 256 gates
constexpr int WPB = 8;                  // windows per block in encoder
constexpr int NWIN = B * T;             // 16384
constexpr int H1S = 20;                 // padded h1 row stride

// scratch
__device__ float g_xg[NWIN * NG];       // 16 MB: xg = feat @ Wih^T + (bih+bhh)
__device__ float g_hs[NWIN * PROJ];     // 4 MB: per-step hidden states

DEVINL void fma2(unsigned long long& d, unsigned long long a, unsigned long long b) {
    asm("fma.rn.f32x2 %0, %1, %2, %0;" : "+l"(d) : "l"(a), "l"(b));
}
DEVINL void add2(unsigned long long& d, unsigned long long a, unsigned long long b) {
    asm("add.rn.f32x2 %0, %1, %2;" : "=l"(d) : "l"(a), "l"(b));
}
DEVINL float hsum2(unsigned long long a) {
    float lo, hi;
    asm("mov.b64 {%0,%1}, %2;" : "=f"(lo), "=f"(hi) : "l"(a));
    return lo + hi;
}
DEVINL unsigned long long pack2(float lo, float hi) {
    unsigned long long r;
    asm("mov.b64 %0, {%1,%2};" : "=l"(r) : "f"(lo), "f"(hi));
    return r;
}

DEVINL float sigm(float x) { return __fdividef(1.f, 1.f + __expf(-x)); }
DEVINL float tanh_(float x) { return __fdividef(2.f, 1.f + __expf(-2.f * x)) - 1.f; }

// ---------------------------------------------------------------------------
// conv1 slice: NPOS contiguous output positions starting at l0, out-ch = lane o.
// Weights in smem transposed [(i*3+k)*32 + o] (lane-stride-1, conflict-free).
// x rows are warp-uniform (broadcast LDS). Rolling-row accumulation.
// ---------------------------------------------------------------------------
template <int NCH, int NPOS>
DEVINL void conv1_go(const float* __restrict__ s_x, const float* __restrict__ s_wT,
                     const float* __restrict__ s_b, float* __restrict__ s_h1,
                     int o, int l0) {
    float acc[NPOS];
    float bv = s_b[o];
#pragma unroll
    for (int j = 0; j < NPOS; j++) acc[j] = bv;
#pragma unroll
    for (int i = 0; i < NCH; i++) {
        float w0 = s_wT[(i * 3 + 0) * 32 + o];
        float w1 = s_wT[(i * 3 + 1) * 32 + o];
        float w2 = s_wT[(i * 3 + 2) * 32 + o];
#pragma unroll
        for (int rr = 0; rr < NPOS + 2; rr++) {
            float x = s_x[(l0 + rr) * NCH + i];
            if (rr < NPOS) acc[rr] = fmaf(x, w0, acc[rr]);
            if (rr >= 1 && rr - 1 < NPOS) acc[rr - 1] = fmaf(x, w1, acc[rr - 1]);
            if (rr >= 2) acc[rr - 2] = fmaf(x, w2, acc[rr - 2]);
        }
    }
#pragma unroll
    for (int j = 0; j < NPOS; j++) s_h1[o * H1S + l0 + j] = fmaxf(acc[j], 0.f);
}

// ---------------------------------------------------------------------------
// conv2 + relu + partial pool: lane = out-ch o, warp-group lgrp = 4 positions.
// h loads warp-uniform (broadcast); w loads lane-stride-1 conflict-free.
// ---------------------------------------------------------------------------
DEVINL void conv2_go(const float* __restrict__ s_h1, const float* __restrict__ s_w2T,
                     const float* __restrict__ s_b2, float* __restrict__ s_part,
                     int o, int lgrp) {
    const int l0 = lgrp * 4;
    float bv = s_b2[o];
    float a0 = bv, a1 = bv, a2 = bv, a3 = bv;
#pragma unroll
    for (int c = 0; c < CC; c++) {
        const float* hp = s_h1 + c * H1S + l0;
        float4 h4 = *reinterpret_cast<const float4*>(hp);
        float2 h2 = *reinterpret_cast<const float2*>(hp + 4);
        float w0 = s_w2T[(c * 3 + 0) * 32 + o];
        float w1 = s_w2T[(c * 3 + 1) * 32 + o];
        float w2 = s_w2T[(c * 3 + 2) * 32 + o];
        a0 = fmaf(h4.x, w0, a0); a0 = fmaf(h4.y, w1, a0); a0 = fmaf(h4.z, w2, a0);
        a1 = fmaf(h4.y, w0, a1); a1 = fmaf(h4.z, w1, a1); a1 = fmaf(h4.w, w2, a1);
        a2 = fmaf(h4.z, w0, a2); a2 = fmaf(h4.w, w1, a2); a2 = fmaf(h2.x, w2, a2);
        a3 = fmaf(h4.w, w0, a3); a3 = fmaf(h2.x, w1, a3); a3 = fmaf(h2.y, w2, a3);
    }
    s_part[lgrp * 32 + o] = fmaxf(a0, 0.f) + fmaxf(a1, 0.f) + fmaxf(a2, 0.f) + fmaxf(a3, 0.f);
}

// ---------------------------------------------------------------------------
// Encoder kernel
// ---------------------------------------------------------------------------
__global__ void __launch_bounds__(256) enc_kernel(
    const float* __restrict__ pressure, const float* __restrict__ torque,
    const float* __restrict__ frag,
    const float* __restrict__ pw1, const float* __restrict__ pb1,
    const float* __restrict__ pw2, const float* __restrict__ pb2,
    const float* __restrict__ tw1, const float* __restrict__ tb1,
    const float* __restrict__ tw2, const float* __restrict__ tb2,
    const float* __restrict__ fw, const float* __restrict__ fb,
    const float* __restrict__ prw, const float* __restrict__ prb,
    const float* __restrict__ Wih, const float* __restrict__ bih,
    const float* __restrict__ bhh) {
    __shared__ float s_w1p[NP * 3 * 32];     // [(i*3+k)*32+o]
    __shared__ float s_w1t[NT * 3 * 32];
    __shared__ float s_w2p[CC * 3 * 32];     // [(c*3+k)*32+o]
    __shared__ float s_w2t[CC * 3 * 32];
    __shared__ float s_b1p[32], s_b1t[32], s_b2p[32], s_b2t[32];
    __shared__ float s_bias[NG];
    __shared__ __align__(16) float s_xp[W * NP];
    __shared__ __align__(16) float s_xt[W * NT];
    __shared__ __align__(16) float s_h1p[CC * H1S];
    __shared__ __align__(16) float s_h1t[CC * H1S];
    __shared__ float s_part[2 * 4 * 32];
    __shared__ float s_red[4 * 64];
    __shared__ __align__(16) float s_cat[2 * CC + FD];
    __shared__ __align__(16) float s_feat[PROJ];

    const int tid = threadIdx.x;
    const int lane = tid & 31;
    const int warp = tid >> 5;

    // ---- stage weights (transposed), once per block ----
    for (int t = tid; t < 32 * NP * 3; t += 256) {   // 576
        int o = t / (NP * 3), r = t % (NP * 3);
        s_w1p[r * 32 + o] = pw1[t];                  // r = i*3+k
    }
    for (int t = tid; t < 32 * NT * 3; t += 256) {   // 1152
        int o = t / (NT * 3), r = t % (NT * 3);
        s_w1t[r * 32 + o] = tw1[t];
    }
    for (int t = tid; t < 32 * CC * 3; t += 256) {   // 3072
        int o = t / (CC * 3), r = t % (CC * 3);
        s_w2p[r * 32 + o] = pw2[t];
        s_w2t[r * 32 + o] = tw2[t];
    }
    if (tid < 32) {
        s_b1p[tid] = pb1[tid]; s_b1t[tid] = tb1[tid];
        s_b2p[tid] = pb2[tid]; s_b2t[tid] = tb2[tid];
    }
    s_bias[tid] = bih[tid] + bhh[tid];
    __syncthreads();

    for (int w = 0; w < WPB; ++w) {
        const int wi = blockIdx.x * WPB + w;
        const int b = wi >> 8;

        // ---- load window inputs ----
        for (int i = tid; i < W * NP; i += 256) s_xp[i] = pressure[wi * (W * NP) + i];
        for (int i = tid; i < W * NT; i += 256) s_xt[i] = torque[wi * (W * NT) + i];
        __syncthreads();

        // ---- conv1 (p: warps 0-2, 6 pos each; t: warps 3-7, 4/4/4/4/2 pos) ----
        if (warp < 3)      conv1_go<NP, 6>(s_xp, s_w1p, s_b1p, s_h1p, lane, warp * 6);
        else if (warp < 7) conv1_go<NT, 4>(s_xt, s_w1t, s_b1t, s_h1t, lane, (warp - 3) * 4);
        else               conv1_go<NT, 2>(s_xt, s_w1t, s_b1t, s_h1t, lane, 16);
        __syncthreads();

        // ---- conv2 (p: warps 0-3, t: warps 4-7) ----
        if (warp < 4) conv2_go(s_h1p, s_w2p, s_b2p, s_part,       lane, warp);
        else          conv2_go(s_h1t, s_w2t, s_b2t, s_part + 128, lane, warp - 4);
        __syncthreads();

        // ---- cat: pooled features + fragility ----
        if (tid < 64) {
            const float* p = s_part + (tid >> 5) * 128 + (tid & 31);
            s_cat[tid] = (p[0] + p[32] + p[64] + p[96]) * (1.f / 16.f);
        } else if (tid < 72) {
            int f = tid - 64;
            s_cat[64 + f] = fmaxf(fmaf(frag[b], fw[f], fb[f]), 0.f);
        }
        __syncthreads();

        // ---- projection (64x72), 4-way split over all 256 threads ----
        {
            int out = tid & 63, part = tid >> 6;
            int base = (part < 2) ? part * 20 : 40 + (part - 2) * 16;
            float acc = 0.f;
            const float4* pr = reinterpret_cast<const float4*>(prw + out * 72 + base);
            const float4* cv = reinterpret_cast<const float4*>(s_cat + base);
            if (part < 2) {
#pragma unroll
                for (int q = 0; q < 5; q++) {
                    float4 wv = pr[q]; float4 xv = cv[q];
                    acc = fmaf(wv.x, xv.x, acc); acc = fmaf(wv.y, xv.y, acc);
                    acc = fmaf(wv.z, xv.z, acc); acc = fmaf(wv.w, xv.w, acc);
                }
            } else {
#pragma unroll
                for (int q = 0; q < 4; q++) {
                    float4 wv = pr[q]; float4 xv = cv[q];
                    acc = fmaf(wv.x, xv.x, acc); acc = fmaf(wv.y, xv.y, acc);
                    acc = fmaf(wv.z, xv.z, acc); acc = fmaf(wv.w, xv.w, acc);
                }
            }
            s_red[part * 64 + out] = acc;
        }
        __syncthreads();
        if (tid < 64)
            s_feat[tid] = fmaxf(s_red[tid] + s_red[64 + tid] + s_red[128 + tid] +
                                s_red[192 + tid] + prb[tid], 0.f);
        __syncthreads();

        // ---- xg = feat @ Wih^T + bias (packed f32x2, FULL 64-elem dot) ----
        {
            unsigned long long a0 = pack2(s_bias[tid], 0.f), a1 = 0ull;
            const ulonglong2* wr = reinterpret_cast<const ulonglong2*>(Wih + tid * PROJ);
            const ulonglong2* fr = reinterpret_cast<const ulonglong2*>(s_feat);
#pragma unroll
            for (int q = 0; q < 16; q++) {        // 16 x 4 floats = 64
                ulonglong2 wv = wr[q]; ulonglong2 fv = fr[q];
                fma2(a0, wv.x, fv.x);
                fma2(a1, wv.y, fv.y);
            }
            add2(a0, a0, a1);
            g_xg[wi * NG + tid] = hsum2(a0);
        }
        __syncthreads();
    }
}

// ---------------------------------------------------------------------------
// LSTM kernel: one block per batch row, 256 threads = one gate each.
// Whh row in f32x2 register pairs; activations done pre-barrier by gate owner;
// h streamed to g_hs (head computed later, out of the serial loop).
// ---------------------------------------------------------------------------
__global__ void __launch_bounds__(256) lstm_kernel(
    const float* __restrict__ Whh, float* __restrict__ out) {
    __shared__ __align__(16) float s_h[PROJ];
    __shared__ float s_gact[NG];

    const int tid = threadIdx.x;
    const int b = blockIdx.x;
    const int cls = tid >> 6;  // 0:i 1:f 2:g 3:o

    unsigned long long wreg[PROJ / 2];
    {
        const ulonglong2* w2 = reinterpret_cast<const ulonglong2*>(Whh + tid * PROJ);
#pragma unroll
        for (int q = 0; q < PROJ / 4; q++) {
            ulonglong2 v = w2[q];
            wreg[2 * q] = v.x;
            wreg[2 * q + 1] = v.y;
        }
    }

    if (tid < PROJ) s_h[tid] = 0.f;
    float c = 0.f;

    const float* xg = g_xg + b * T * NG;
    float* hs = g_hs + b * T * PROJ;
    float xnext = xg[tid];
    __syncthreads();

    for (int t = 0; t < T; t++) {
        float xcur = xnext;
        int tn = (t + 1 < T) ? (t + 1) : (T - 1);
        xnext = xg[tn * NG + tid];

        // FULL 64-elem dot: 16 x ulonglong2 (4 floats each)
        unsigned long long a0 = pack2(xcur, 0.f), a1 = 0ull, a2 = 0ull, a3 = 0ull;
        const ulonglong2* h2 = reinterpret_cast<const ulonglong2*>(s_h);
#pragma unroll
        for (int q = 0; q < 16; q++) {
            ulonglong2 hv = h2[q];
            if ((q & 1) == 0) { fma2(a0, wreg[2 * q], hv.x); fma2(a1, wreg[2 * q + 1], hv.y); }
            else              { fma2(a2, wreg[2 * q], hv.x); fma2(a3, wreg[2 * q + 1], hv.y); }
        }
        add2(a0, a0, a2);
        add2(a1, a1, a3);
        add2(a0, a0, a1);
        float g = hsum2(a0);
        s_gact[tid] = (cls == 2) ? tanh_(g) : sigm(g);
        __syncthreads();

        if (tid < PROJ) {
            float ai = s_gact[tid];
            float af = s_gact[PROJ + tid];
            float ag = s_gact[2 * PROJ + tid];
            float ao = s_gact[3 * PROJ + tid];
            c = fmaf(af, c, ai * ag);
            float h = ao * tanh_(c);
            s_h[tid] = h;
            hs[t * PROJ + tid] = h;
        }
        __syncthreads();
    }

    if (tid < PROJ) {
        out[B * T * 4 + b * PROJ + tid] = s_h[tid];             // hT
        out[B * T * 4 + B * PROJ + b * PROJ + tid] = c;         // cT
    }
}

// ---------------------------------------------------------------------------
// Head kernel: out[wi, m] = sigmoid(h[wi] . hw[m] + hb[m]), fully parallel.
// ---------------------------------------------------------------------------
__global__ void __launch_bounds__(256) head_kernel(
    const float* __restrict__ hw, const float* __restrict__ hb,
    float* __restrict__ out) {
    __shared__ __align__(16) float s_hw[4 * PROJ];
    __shared__ float s_hb[4];
    const int tid = threadIdx.x;
    s_hw[tid] = hw[tid];
    if (tid < 4) s_hb[tid] = hb[tid];
    __syncthreads();

    const int gid = blockIdx.x * 256 + tid;
    const int wi = gid >> 2, m = gid & 3;
    const float4* hr = reinterpret_cast<const float4*>(g_hs + wi * PROJ);
    const float4* wr = reinterpret_cast<const float4*>(s_hw) + m * 16;
    float a0 = s_hb[m], a1 = 0.f;
#pragma unroll
    for (int q = 0; q < 16; q += 2) {
        float4 h0 = hr[q], w0 = wr[q];
        float4 h1 = hr[q + 1], w1 = wr[q + 1];
        a0 = fmaf(h0.x, w0.x, a0); a0 = fmaf(h0.y, w0.y, a0);
        a0 = fmaf(h0.z, w0.z, a0); a0 = fmaf(h0.w, w0.w, a0);
        a1 = fmaf(h1.x, w1.x, a1); a1 = fmaf(h1.y, w1.y, a1);
        a1 = fmaf(h1.z, w1.z, a1); a1 = fmaf(h1.w, w1.w, a1);
    }
    out[gid] = sigm(a0 + a1);
}

// ---------------------------------------------------------------------------
extern "C" void kernel_launch(void* const* d_in, const int* in_sizes, int n_in,
                              void* d_out, int out_size) {
    const float* pressure = (const float*)d_in[0];
    const float* torque   = (const float*)d_in[1];
    const float* frag     = (const float*)d_in[2];
    const float* pw1 = (const float*)d_in[3];
    const float* pb1 = (const float*)d_in[4];
    const float* pw2 = (const float*)d_in[5];
    const float* pb2 = (const float*)d_in[6];
    const float* tw1 = (const float*)d_in[7];
    const float* tb1 = (const float*)d_in[8];
    const float* tw2 = (const float*)d_in[9];
    const float* tb2 = (const float*)d_in[10];
    const float* fw  = (const float*)d_in[11];
    const float* fb  = (const float*)d_in[12];
    const float* prw = (const float*)d_in[13];
    const float* prb = (const float*)d_in[14];
    const float* Wih = (const float*)d_in[15];
    const float* Whh = (const float*)d_in[16];
    const float* bih = (const float*)d_in[17];
    const float* bhh = (const float*)d_in[18];
    const float* hw  = (const float*)d_in[19];
    const float* hb  = (const float*)d_in[20];

    enc_kernel<<<NWIN / WPB, 256>>>(pressure, torque, frag,
                                    pw1, pb1, pw2, pb2, tw1, tb1, tw2, tb2,
                                    fw, fb, prw, prb, Wih, bih, bhh);
    lstm_kernel<<<B, 256>>>(Whh, (float*)d_out);
    head_kernel<<<(B * T * 4) / 256, 256>>>(hw, hb, (float*)d_out);
}

// round 4
// speedup vs baseline: 2.7981x; 2.7981x over previous
#include <cuda_runtime.h>

#define DEVINL __device__ __forceinline__
typedef unsigned long long ull;

constexpr int B = 64, T = 256, W = 20, NP = 6, NT = 12, CC = 32, FD = 8, PROJ = 64;
constexpr int NG = 4 * PROJ;            // 256 gates
constexpr int NWIN = B * T;             // 16384

// scratch
__device__ float g_xg[NWIN * NG];       // 16 MB: xg = feat @ Wih^T + (bih+bhh)
__device__ float g_hs[NWIN * PROJ];     // 4 MB: per-step hidden states

DEVINL void fma2(ull& d, ull a, ull b) {
    asm("fma.rn.f32x2 %0, %1, %2, %0;" : "+l"(d) : "l"(a), "l"(b));
}
DEVINL void add2(ull& d, ull a, ull b) {
    asm("add.rn.f32x2 %0, %1, %2;" : "=l"(d) : "l"(a), "l"(b));
}
DEVINL float hsum2(ull a) {
    float lo, hi;
    asm("mov.b64 {%0,%1}, %2;" : "=f"(lo), "=f"(hi) : "l"(a));
    return lo + hi;
}
DEVINL ull pack2(float lo, float hi) {
    ull r;
    asm("mov.b64 %0, {%1,%2};" : "=l"(r) : "f"(lo), "f"(hi));
    return r;
}
DEVINL void upk(ull a, float& lo, float& hi) {
    asm("mov.b64 {%0,%1}, %2;" : "=f"(lo), "=f"(hi) : "l"(a));
}

DEVINL float sigm(float x) { return __fdividef(1.f, 1.f + __expf(-x)); }
DEVINL float tanh_(float x) { return __fdividef(2.f, 1.f + __expf(-2.f * x)) - 1.f; }

// ---------------------------------------------------------------------------
// smem layout (floats) — dynamic shared
// ---------------------------------------------------------------------------
constexpr int OFF_W1P = 0;                        // 1152  dup (w,w): [(3i+k)*32+o]*2
constexpr int OFF_W1T = OFF_W1P + 1152;           // 2304
constexpr int OFF_W2P = OFF_W1T + 2304;           // 6144
constexpr int OFF_W2T = OFF_W2P + 6144;           // 6144
constexpr int OFF_B1P = OFF_W2T + 6144;           // 32
constexpr int OFF_B1T = OFF_B1P + 32;             // 32
constexpr int OFF_B2P = OFF_B1T + 32;             // 32
constexpr int OFF_B2T = OFF_B2P + 32;             // 32
constexpr int OFF_BIAS = OFF_B2T + 32;            // 256
constexpr int OFF_X   = OFF_BIAS + 256;           // 8 * 256
constexpr int OFF_H1  = OFF_X + 8 * 256;          // 8 * 640 (32 rows x 20)
constexpr int OFF_CAT = OFF_H1 + 8 * 640;         // 8 * 80
constexpr int OFF_PRJ = OFF_CAT + 8 * 80;         // 8 * 64
constexpr int SMEM_FLOATS = OFF_PRJ + 8 * 64;     // 24448 floats
constexpr int SMEM_BYTES = SMEM_FLOATS * 4;       // 97792 B

// ---------------------------------------------------------------------------
// Fused conv pass with packed f32x2 over position pairs.
//   in rows: s_in[c*20 + l], 20 floats/row (values at l>=valid are zero)
//   weights: s_w2 pre-offset by 2*o; entry ((3c+k)*64) is packed (w,w)
//   NACC2 = 9 -> 18 outputs (conv1, store to h1row), 8 -> 16 outputs (conv2, pool)
// ---------------------------------------------------------------------------
template <int NIN, int NACC2, bool STORE>
DEVINL void conv_pass(const float* __restrict__ s_in, const float* __restrict__ s_w2,
                      float bv, float* __restrict__ h1row, float* __restrict__ pool_dst) {
    ull acc[NACC2];
    ull bb = pack2(bv, bv);
#pragma unroll
    for (int p = 0; p < NACC2; p++) acc[p] = bb;

#pragma unroll 4
    for (int c = 0; c < NIN; c++) {
        const float4* rp = reinterpret_cast<const float4*>(s_in + c * 20);
        float r[20];
        *reinterpret_cast<float4*>(r +  0) = rp[0];
        *reinterpret_cast<float4*>(r +  4) = rp[1];
        *reinterpret_cast<float4*>(r +  8) = rp[2];
        *reinterpret_cast<float4*>(r + 12) = rp[3];
        *reinterpret_cast<float4*>(r + 16) = rp[4];

        const ull* wp = reinterpret_cast<const ull*>(s_w2 + (3 * c) * 64);
        ull w0p = wp[0];                 // entries are 64 floats apart -> ull idx 32
        ull w1p = *reinterpret_cast<const ull*>(s_w2 + (3 * c + 1) * 64);
        ull w2p = *reinterpret_cast<const ull*>(s_w2 + (3 * c + 2) * 64);

        ull e[NACC2 + 1], od[NACC2];
#pragma unroll
        for (int j = 0; j <= NACC2; j++) e[j] = pack2(r[2 * j], r[2 * j + 1]);
#pragma unroll
        for (int j = 0; j < NACC2; j++) od[j] = pack2(r[2 * j + 1], r[2 * j + 2]);

#pragma unroll
        for (int p = 0; p < NACC2; p++) {
            fma2(acc[p], e[p], w0p);
            fma2(acc[p], od[p], w1p);
            fma2(acc[p], e[p + 1], w2p);
        }
    }

    if (STORE) {
#pragma unroll
        for (int p = 0; p < NACC2; p++) {
            float lo, hi; upk(acc[p], lo, hi);
            h1row[2 * p] = fmaxf(lo, 0.f);
            h1row[2 * p + 1] = fmaxf(hi, 0.f);
        }
        h1row[18] = 0.f;
        h1row[19] = 0.f;
    } else {
        float s = 0.f;
#pragma unroll
        for (int p = 0; p < NACC2; p++) {
            float lo, hi; upk(acc[p], lo, hi);
            s += fmaxf(lo, 0.f) + fmaxf(hi, 0.f);
        }
        *pool_dst = s * (1.f / 16.f);
    }
}

// ---------------------------------------------------------------------------
// Encoder kernel: warp = one window. No inter-warp dependency until xg phase.
// ---------------------------------------------------------------------------
__global__ void __launch_bounds__(256) enc_kernel(
    const float* __restrict__ pressure, const float* __restrict__ torque,
    const float* __restrict__ frag,
    const float* __restrict__ pw1, const float* __restrict__ pb1,
    const float* __restrict__ pw2, const float* __restrict__ pb2,
    const float* __restrict__ tw1, const float* __restrict__ tb1,
    const float* __restrict__ tw2, const float* __restrict__ tb2,
    const float* __restrict__ fw, const float* __restrict__ fb,
    const float* __restrict__ prw, const float* __restrict__ prb,
    const float* __restrict__ Wih, const float* __restrict__ bih,
    const float* __restrict__ bhh) {
    extern __shared__ float sm[];
    const int tid = threadIdx.x;
    const int lane = tid & 31;
    const int warp = tid >> 5;

    // ---- stage weights (transposed + duplicated (w,w)) ----
    for (int t = tid; t < 32 * NP * 3; t += 256) {        // 576
        int o = t / (NP * 3), r = t % (NP * 3);
        float v = pw1[t];
        int di = (r * 32 + o) * 2;
        sm[OFF_W1P + di] = v; sm[OFF_W1P + di + 1] = v;
    }
    for (int t = tid; t < 32 * NT * 3; t += 256) {        // 1152
        int o = t / (NT * 3), r = t % (NT * 3);
        float v = tw1[t];
        int di = (r * 32 + o) * 2;
        sm[OFF_W1T + di] = v; sm[OFF_W1T + di + 1] = v;
    }
    for (int t = tid; t < 32 * CC * 3; t += 256) {        // 3072
        int o = t / (CC * 3), r = t % (CC * 3);
        int di = (r * 32 + o) * 2;
        float vp = pw2[t], vt = tw2[t];
        sm[OFF_W2P + di] = vp; sm[OFF_W2P + di + 1] = vp;
        sm[OFF_W2T + di] = vt; sm[OFF_W2T + di + 1] = vt;
    }
    if (tid < 32) {
        sm[OFF_B1P + tid] = pb1[tid]; sm[OFF_B1T + tid] = tb1[tid];
        sm[OFF_B2P + tid] = pb2[tid]; sm[OFF_B2T + tid] = tb2[tid];
    }
    sm[OFF_BIAS + tid] = bih[tid] + bhh[tid];
    __syncthreads();

    const int wi = blockIdx.x * 8 + warp;
    const int b = wi >> 8;

    float* sx  = sm + OFF_X   + warp * 256;
    float* sh1 = sm + OFF_H1  + warp * 640;
    float* sft = sm + OFF_CAT + warp * 80;
    float* spj = sm + OFF_PRJ + warp * 64;

    // ---- prefetch window inputs into registers ----
    float xp_r[4], xt_r[8];
    const float* gp = pressure + wi * (W * NP);
    const float* gt = torque + wi * (W * NT);
#pragma unroll
    for (int k = 0; k < 4; k++) {
        int idx = lane + 32 * k;
        xp_r[k] = (idx < W * NP) ? gp[idx] : 0.f;
    }
#pragma unroll
    for (int k = 0; k < 8; k++) {
        int idx = lane + 32 * k;
        xt_r[k] = (idx < W * NT) ? gt[idx] : 0.f;
    }

    // ---- store pressure transposed [i][l] ----
#pragma unroll
    for (int k = 0; k < 4; k++) {
        int idx = lane + 32 * k;
        if (idx < W * NP) { int l = idx / NP, i = idx % NP; sx[i * 20 + l] = xp_r[k]; }
    }
    __syncwarp();

    // ---- conv1-p -> h1 ----
    conv_pass<NP, 9, true>(sx, sm + OFF_W1P + 2 * lane, sm[OFF_B1P + lane],
                           sh1 + lane * 20, nullptr);
    __syncwarp();

    // ---- store torque transposed (sx reads done), then conv2-p ----
#pragma unroll
    for (int k = 0; k < 8; k++) {
        int idx = lane + 32 * k;
        if (idx < W * NT) { int l = idx / NT, i = idx % NT; sx[i * 20 + l] = xt_r[k]; }
    }
    conv_pass<CC, 8, false>(sh1, sm + OFF_W2P + 2 * lane, sm[OFF_B2P + lane],
                            nullptr, sft + lane);
    __syncwarp();

    // ---- conv1-t -> h1 ----
    conv_pass<NT, 9, true>(sx, sm + OFF_W1T + 2 * lane, sm[OFF_B1T + lane],
                           sh1 + lane * 20, nullptr);
    __syncwarp();

    // ---- conv2-t ----
    conv_pass<CC, 8, false>(sh1, sm + OFF_W2T + 2 * lane, sm[OFF_B2T + lane],
                            nullptr, sft + 32 + lane);

    // ---- fragility ----
    if (lane < FD) sft[64 + lane] = fmaxf(fmaf(frag[b], fw[lane], fb[lane]), 0.f);
    __syncwarp();

    // ---- projection: 2 outputs per lane, dot-72 ----
    {
        float a0 = prb[lane], a1 = prb[lane + 32];
        const float4* w0 = reinterpret_cast<const float4*>(prw + lane * 72);
        const float4* w1 = reinterpret_cast<const float4*>(prw + (lane + 32) * 72);
        const float4* cv = reinterpret_cast<const float4*>(sft);
#pragma unroll
        for (int q = 0; q < 18; q++) {
            float4 xv = cv[q];
            float4 u = w0[q], v = w1[q];
            a0 = fmaf(u.x, xv.x, a0); a0 = fmaf(u.y, xv.y, a0);
            a0 = fmaf(u.z, xv.z, a0); a0 = fmaf(u.w, xv.w, a0);
            a1 = fmaf(v.x, xv.x, a1); a1 = fmaf(v.y, xv.y, a1);
            a1 = fmaf(v.z, xv.z, a1); a1 = fmaf(v.w, xv.w, a1);
        }
        spj[lane] = fmaxf(a0, 0.f);
        spj[lane + 32] = fmaxf(a1, 0.f);
    }
    __syncthreads();

    // ---- xg: gate tid for all 8 windows; Wih row held in registers ----
    {
        ull wv[32];
        const ulonglong2* wr = reinterpret_cast<const ulonglong2*>(Wih + tid * PROJ);
#pragma unroll
        for (int q = 0; q < 16; q++) {
            ulonglong2 v = wr[q];
            wv[2 * q] = v.x; wv[2 * q + 1] = v.y;
        }
        float bias = sm[OFF_BIAS + tid];
        const int wbase = blockIdx.x * 8;
#pragma unroll 2
        for (int win = 0; win < 8; win++) {
            const ulonglong2* fr = reinterpret_cast<const ulonglong2*>(sm + OFF_PRJ + win * 64);
            ull a0 = pack2(bias, 0.f), a1 = 0ull, a2 = 0ull, a3 = 0ull;
#pragma unroll
            for (int q = 0; q < 16; q++) {
                ulonglong2 fv = fr[q];
                if ((q & 1) == 0) { fma2(a0, wv[2 * q], fv.x); fma2(a1, wv[2 * q + 1], fv.y); }
                else              { fma2(a2, wv[2 * q], fv.x); fma2(a3, wv[2 * q + 1], fv.y); }
            }
            add2(a0, a0, a2);
            add2(a1, a1, a3);
            add2(a0, a0, a1);
            g_xg[(wbase + win) * NG + tid] = hsum2(a0);
        }
    }
}

// ---------------------------------------------------------------------------
// LSTM kernel (round-3, correct): one block per batch row, 256 threads = gates.
// ---------------------------------------------------------------------------
__global__ void __launch_bounds__(256) lstm_kernel(
    const float* __restrict__ Whh, float* __restrict__ out) {
    __shared__ __align__(16) float s_h[PROJ];
    __shared__ float s_gact[NG];

    const int tid = threadIdx.x;
    const int b = blockIdx.x;
    const int cls = tid >> 6;  // 0:i 1:f 2:g 3:o

    ull wreg[PROJ / 2];
    {
        const ulonglong2* w2 = reinterpret_cast<const ulonglong2*>(Whh + tid * PROJ);
#pragma unroll
        for (int q = 0; q < PROJ / 4; q++) {
            ulonglong2 v = w2[q];
            wreg[2 * q] = v.x;
            wreg[2 * q + 1] = v.y;
        }
    }

    if (tid < PROJ) s_h[tid] = 0.f;
    float c = 0.f;

    const float* xg = g_xg + b * T * NG;
    float* hs = g_hs + b * T * PROJ;
    float xnext = xg[tid];
    __syncthreads();

    for (int t = 0; t < T; t++) {
        float xcur = xnext;
        int tn = (t + 1 < T) ? (t + 1) : (T - 1);
        xnext = xg[tn * NG + tid];

        ull a0 = pack2(xcur, 0.f), a1 = 0ull, a2 = 0ull, a3 = 0ull;
        const ulonglong2* h2 = reinterpret_cast<const ulonglong2*>(s_h);
#pragma unroll
        for (int q = 0; q < 16; q++) {
            ulonglong2 hv = h2[q];
            if ((q & 1) == 0) { fma2(a0, wreg[2 * q], hv.x); fma2(a1, wreg[2 * q + 1], hv.y); }
            else              { fma2(a2, wreg[2 * q], hv.x); fma2(a3, wreg[2 * q + 1], hv.y); }
        }
        add2(a0, a0, a2);
        add2(a1, a1, a3);
        add2(a0, a0, a1);
        float g = hsum2(a0);
        s_gact[tid] = (cls == 2) ? tanh_(g) : sigm(g);
        __syncthreads();

        if (tid < PROJ) {
            float ai = s_gact[tid];
            float af = s_gact[PROJ + tid];
            float ag = s_gact[2 * PROJ + tid];
            float ao = s_gact[3 * PROJ + tid];
            c = fmaf(af, c, ai * ag);
            float h = ao * tanh_(c);
            s_h[tid] = h;
            hs[t * PROJ + tid] = h;
        }
        __syncthreads();
    }

    if (tid < PROJ) {
        out[B * T * 4 + b * PROJ + tid] = s_h[tid];             // hT
        out[B * T * 4 + B * PROJ + b * PROJ + tid] = c;         // cT
    }
}

// ---------------------------------------------------------------------------
// Head kernel: out[wi, m] = sigmoid(h[wi] . hw[m] + hb[m]), fully parallel.
// ---------------------------------------------------------------------------
__global__ void __launch_bounds__(256) head_kernel(
    const float* __restrict__ hw, const float* __restrict__ hb,
    float* __restrict__ out) {
    __shared__ __align__(16) float s_hw[4 * PROJ];
    __shared__ float s_hb[4];
    const int tid = threadIdx.x;
    s_hw[tid] = hw[tid];
    if (tid < 4) s_hb[tid] = hb[tid];
    __syncthreads();

    const int gid = blockIdx.x * 256 + tid;
    const int wi = gid >> 2, m = gid & 3;
    const float4* hr = reinterpret_cast<const float4*>(g_hs + wi * PROJ);
    const float4* wr = reinterpret_cast<const float4*>(s_hw) + m * 16;
    float a0 = s_hb[m], a1 = 0.f;
#pragma unroll
    for (int q = 0; q < 16; q += 2) {
        float4 h0 = hr[q], w0 = wr[q];
        float4 h1 = hr[q + 1], w1 = wr[q + 1];
        a0 = fmaf(h0.x, w0.x, a0); a0 = fmaf(h0.y, w0.y, a0);
        a0 = fmaf(h0.z, w0.z, a0); a0 = fmaf(h0.w, w0.w, a0);
        a1 = fmaf(h1.x, w1.x, a1); a1 = fmaf(h1.y, w1.y, a1);
        a1 = fmaf(h1.z, w1.z, a1); a1 = fmaf(h1.w, w1.w, a1);
    }
    out[gid] = sigm(a0 + a1);
}

// ---------------------------------------------------------------------------
extern "C" void kernel_launch(void* const* d_in, const int* in_sizes, int n_in,
                              void* d_out, int out_size) {
    const float* pressure = (const float*)d_in[0];
    const float* torque   = (const float*)d_in[1];
    const float* frag     = (const float*)d_in[2];
    const float* pw1 = (const float*)d_in[3];
    const float* pb1 = (const float*)d_in[4];
    const float* pw2 = (const float*)d_in[5];
    const float* pb2 = (const float*)d_in[6];
    const float* tw1 = (const float*)d_in[7];
    const float* tb1 = (const float*)d_in[8];
    const float* tw2 = (const float*)d_in[9];
    const float* tb2 = (const float*)d_in[10];
    const float* fw  = (const float*)d_in[11];
    const float* fb  = (const float*)d_in[12];
    const float* prw = (const float*)d_in[13];
    const float* prb = (const float*)d_in[14];
    const float* Wih = (const float*)d_in[15];
    const float* Whh = (const float*)d_in[16];
    const float* bih = (const float*)d_in[17];
    const float* bhh = (const float*)d_in[18];
    const float* hw  = (const float*)d_in[19];
    const float* hb  = (const float*)d_in[20];

    static bool attr_set = false;
    if (!attr_set) {
        cudaFuncSetAttribute(enc_kernel, cudaFuncAttributeMaxDynamicSharedMemorySize,
                             SMEM_BYTES);
        attr_set = true;
    }

    enc_kernel<<<NWIN / 8, 256, SMEM_BYTES>>>(pressure, torque, frag,
                                              pw1, pb1, pw2, pb2, tw1, tb1, tw2, tb2,
                                              fw, fb, prw, prb, Wih, bih, bhh);
    lstm_kernel<<<B, 256>>>(Whh, (float*)d_out);
    head_kernel<<<(B * T * 4) / 256, 256>>>(hw, hb, (float*)d_out);
}

// round 5
// speedup vs baseline: 2.9086x; 1.0395x over previous
#include <cuda_runtime.h>

#define DEVINL __device__ __forceinline__
typedef unsigned long long ull;

constexpr int B = 64, T = 256, W = 20, NP = 6, NT = 12, CC = 32, FD = 8, PROJ = 64;
constexpr int NG = 4 * PROJ;            // 256 gates
constexpr int NWIN = B * T;             // 16384

// scratch
__device__ float g_xg[NWIN * NG];       // 16 MB: xg = feat @ Wih^T + (bih+bhh)
__device__ float g_hs[NWIN * PROJ];     // 4 MB: per-step hidden states

DEVINL void fma2(ull& d, ull a, ull b) {
    asm("fma.rn.f32x2 %0, %1, %2, %0;" : "+l"(d) : "l"(a), "l"(b));
}
DEVINL void add2(ull& d, ull a, ull b) {
    asm("add.rn.f32x2 %0, %1, %2;" : "=l"(d) : "l"(a), "l"(b));
}
DEVINL float hsum2(ull a) {
    float lo, hi;
    asm("mov.b64 {%0,%1}, %2;" : "=f"(lo), "=f"(hi) : "l"(a));
    return lo + hi;
}
DEVINL ull pack2(float lo, float hi) {
    ull r;
    asm("mov.b64 %0, {%1,%2};" : "=l"(r) : "f"(lo), "f"(hi));
    return r;
}

DEVINL float sigm(float x) { return __fdividef(1.f, 1.f + __expf(-x)); }
DEVINL float tanh_(float x) { return __fdividef(2.f, 1.f + __expf(-2.f * x)) - 1.f; }

// ---------------------------------------------------------------------------
// smem layout (floats) — dynamic shared
// Conv weights staged as CHANNEL-PAIRS: entry [(3m+k)*64 + 2o] = (w[o][2m][k], w[o][2m+1][k])
// ---------------------------------------------------------------------------
constexpr int OFF_W1P  = 0;                       // 3m x 3k x 64 = 576
constexpr int OFF_W1T  = OFF_W1P + 576;           // 6 x 3 x 64 = 1152
constexpr int OFF_W2P  = OFF_W1T + 1152;          // 16 x 3 x 64 = 3072
constexpr int OFF_W2T  = OFF_W2P + 3072;          // 3072
constexpr int OFF_B1P  = OFF_W2T + 3072;          // 32
constexpr int OFF_B1T  = OFF_B1P + 32;            // 32
constexpr int OFF_B2P  = OFF_B1T + 32;            // 32
constexpr int OFF_B2T  = OFF_B2P + 32;            // 32
constexpr int OFF_BIAS = OFF_B2T + 32;            // 256
constexpr int OFF_XP   = OFF_BIAS + 256;          // 8 * 128  (x[l*6+i], raw layout)
constexpr int OFF_XT   = OFF_XP + 8 * 128;        // 8 * 256  (x[l*12+i])
constexpr int OFF_H1   = OFF_XT + 8 * 256;        // 8 * 576  (h1T[j*32+o])
constexpr int OFF_CAT  = OFF_H1 + 8 * 576;        // 8 * 80
constexpr int OFF_PRJ  = OFF_CAT + 8 * 80;        // 8 * 64
constexpr int SMEM_FLOATS = OFF_PRJ + 8 * 64;     // 17088
constexpr int SMEM_BYTES = SMEM_FLOATS * 4;       // 68352 B

// ---------------------------------------------------------------------------
// conv1 over channel pairs: input s_x[j*STRIDE + c] (raw [pos][ch] layout),
// weights s_w pre-offset by 2*lane, output h1T[j*32] (pre-offset by lane).
// out[o][j] = relu(hsum2(acc[j]) + b), j = 0..17.
// ---------------------------------------------------------------------------
template <int NPAIR, int STRIDE>
DEVINL void conv1T(const float* __restrict__ s_x, const float* __restrict__ s_w,
                   float bv, float* __restrict__ h1T) {
    ull acc[18];
#pragma unroll
    for (int j = 0; j < 18; j++) acc[j] = 0ull;

#pragma unroll
    for (int m = 0; m < NPAIR; m++) {
        ull w0 = *reinterpret_cast<const ull*>(s_w + (3 * m + 0) * 64);
        ull w1 = *reinterpret_cast<const ull*>(s_w + (3 * m + 1) * 64);
        ull w2 = *reinterpret_cast<const ull*>(s_w + (3 * m + 2) * 64);
#pragma unroll
        for (int j = 0; j < 20; j++) {
            ull v = *reinterpret_cast<const ull*>(s_x + j * STRIDE + 2 * m);
            if (j < 18) fma2(acc[j], v, w0);
            if (j >= 1 && j <= 18) fma2(acc[j - 1], v, w1);
            if (j >= 2) fma2(acc[j - 2], v, w2);
        }
    }
#pragma unroll
    for (int j = 0; j < 18; j++)
        h1T[j * 32] = fmaxf(hsum2(acc[j]) + bv, 0.f);
}

// ---------------------------------------------------------------------------
// conv2 over channel pairs + relu + mean pool. Input h1T[j*32 + c] (warp base).
// Returns pooled mean over 16 positions for out-channel = lane.
// ---------------------------------------------------------------------------
DEVINL float conv2T(const float* __restrict__ h1T, const float* __restrict__ s_w,
                    float bv) {
    ull acc[16];
#pragma unroll
    for (int j = 0; j < 16; j++) acc[j] = 0ull;

#pragma unroll 4
    for (int m = 0; m < 16; m++) {
        ull w0 = *reinterpret_cast<const ull*>(s_w + (3 * m + 0) * 64);
        ull w1 = *reinterpret_cast<const ull*>(s_w + (3 * m + 1) * 64);
        ull w2 = *reinterpret_cast<const ull*>(s_w + (3 * m + 2) * 64);
#pragma unroll
        for (int j = 0; j < 18; j++) {
            ull v = *reinterpret_cast<const ull*>(h1T + j * 32 + 2 * m);
            if (j < 16) fma2(acc[j], v, w0);
            if (j >= 1 && j <= 16) fma2(acc[j - 1], v, w1);
            if (j >= 2) fma2(acc[j - 2], v, w2);
        }
    }
    float s = 0.f;
#pragma unroll
    for (int j = 0; j < 16; j++)
        s += fmaxf(hsum2(acc[j]) + bv, 0.f);
    return s * (1.f / 16.f);
}

// ---------------------------------------------------------------------------
// Encoder kernel: warp = one window.
// ---------------------------------------------------------------------------
__global__ void __launch_bounds__(256) enc_kernel(
    const float* __restrict__ pressure, const float* __restrict__ torque,
    const float* __restrict__ frag,
    const float* __restrict__ pw1, const float* __restrict__ pb1,
    const float* __restrict__ pw2, const float* __restrict__ pb2,
    const float* __restrict__ tw1, const float* __restrict__ tb1,
    const float* __restrict__ tw2, const float* __restrict__ tb2,
    const float* __restrict__ fw, const float* __restrict__ fb,
    const float* __restrict__ prw, const float* __restrict__ prb,
    const float* __restrict__ Wih, const float* __restrict__ bih,
    const float* __restrict__ bhh) {
    extern __shared__ float sm[];
    const int tid = threadIdx.x;
    const int lane = tid & 31;
    const int warp = tid >> 5;

    // ---- stage channel-pair weights ----
    for (int t = tid; t < 32 * 3 * 3; t += 256) {         // 288: o x m(3) x k(3)
        int o = t / 9, rem = t % 9, m = rem / 3, k = rem % 3;
        int di = OFF_W1P + (3 * m + k) * 64 + 2 * o;
        sm[di]     = pw1[(o * NP + 2 * m) * 3 + k];
        sm[di + 1] = pw1[(o * NP + 2 * m + 1) * 3 + k];
    }
    for (int t = tid; t < 32 * 6 * 3; t += 256) {         // 576: o x m(6) x k(3)
        int o = t / 18, rem = t % 18, m = rem / 3, k = rem % 3;
        int di = OFF_W1T + (3 * m + k) * 64 + 2 * o;
        sm[di]     = tw1[(o * NT + 2 * m) * 3 + k];
        sm[di + 1] = tw1[(o * NT + 2 * m + 1) * 3 + k];
    }
    for (int t = tid; t < 32 * 16 * 3; t += 256) {        // 1536: o x m(16) x k(3)
        int o = t / 48, rem = t % 48, m = rem / 3, k = rem % 3;
        int di = (3 * m + k) * 64 + 2 * o;
        int si0 = (o * CC + 2 * m) * 3 + k, si1 = (o * CC + 2 * m + 1) * 3 + k;
        sm[OFF_W2P + di]     = pw2[si0];
        sm[OFF_W2P + di + 1] = pw2[si1];
        sm[OFF_W2T + di]     = tw2[si0];
        sm[OFF_W2T + di + 1] = tw2[si1];
    }
    if (tid < 32) {
        sm[OFF_B1P + tid] = pb1[tid]; sm[OFF_B1T + tid] = tb1[tid];
        sm[OFF_B2P + tid] = pb2[tid]; sm[OFF_B2T + tid] = tb2[tid];
    }
    sm[OFF_BIAS + tid] = bih[tid] + bhh[tid];
    __syncthreads();

    const int wi = blockIdx.x * 8 + warp;
    const int b = wi >> 8;

    float* sxp = sm + OFF_XP + warp * 128;
    float* sxt = sm + OFF_XT + warp * 256;
    float* sh1 = sm + OFF_H1 + warp * 576;
    float* sft = sm + OFF_CAT + warp * 80;
    float* spj = sm + OFF_PRJ + warp * 64;

    // ---- load window inputs (raw [pos][ch] layout kept) ----
    {
        const float4* gp4 = reinterpret_cast<const float4*>(pressure + wi * 120);
        if (lane < 30) reinterpret_cast<float4*>(sxp)[lane] = gp4[lane];
        const float4* gt4 = reinterpret_cast<const float4*>(torque + wi * 240);
        reinterpret_cast<float4*>(sxt)[lane] = gt4[lane];
        if (lane < 28) reinterpret_cast<float4*>(sxt)[lane + 32] = gt4[lane + 32];
    }
    __syncwarp();

    // ---- pressure: conv1 -> h1T -> conv2 -> pooled ----
    conv1T<3, NP>(sxp, sm + OFF_W1P + 2 * lane, sm[OFF_B1P + lane], sh1 + lane);
    __syncwarp();
    float poolp = conv2T(sh1, sm + OFF_W2P + 2 * lane, sm[OFF_B2P + lane]);
    __syncwarp();        // all reads of h1 done before torque overwrites

    // ---- torque: conv1 -> h1T -> conv2 -> pooled ----
    conv1T<6, NT>(sxt, sm + OFF_W1T + 2 * lane, sm[OFF_B1T + lane], sh1 + lane);
    __syncwarp();
    float poolt = conv2T(sh1, sm + OFF_W2T + 2 * lane, sm[OFF_B2T + lane]);

    sft[lane] = poolp;
    sft[32 + lane] = poolt;
    if (lane < FD) sft[64 + lane] = fmaxf(fmaf(frag[b], fw[lane], fb[lane]), 0.f);
    __syncwarp();

    // ---- projection: 2 outputs per lane, packed dot-72 ----
    {
        ull a0 = 0ull, a1 = 0ull, b0 = 0ull, b1 = 0ull;
        const ull* w0 = reinterpret_cast<const ull*>(prw + lane * 72);
        const ull* w1 = reinterpret_cast<const ull*>(prw + (lane + 32) * 72);
        const ull* cv = reinterpret_cast<const ull*>(sft);
#pragma unroll
        for (int q = 0; q < 36; q += 2) {
            ull x0 = cv[q], x1 = cv[q + 1];
            fma2(a0, w0[q], x0); fma2(b0, w0[q + 1], x1);
            fma2(a1, w1[q], x0); fma2(b1, w1[q + 1], x1);
        }
        add2(a0, a0, b0);
        add2(a1, a1, b1);
        spj[lane]      = fmaxf(hsum2(a0) + prb[lane], 0.f);
        spj[lane + 32] = fmaxf(hsum2(a1) + prb[lane + 32], 0.f);
    }
    __syncthreads();

    // ---- xg: gate tid for all 8 windows; Wih row held in registers ----
    {
        ull wv[32];
        const ulonglong2* wr = reinterpret_cast<const ulonglong2*>(Wih + tid * PROJ);
#pragma unroll
        for (int q = 0; q < 16; q++) {
            ulonglong2 v = wr[q];
            wv[2 * q] = v.x; wv[2 * q + 1] = v.y;
        }
        float bias = sm[OFF_BIAS + tid];
        const int wbase = blockIdx.x * 8;
#pragma unroll 2
        for (int win = 0; win < 8; win++) {
            const ulonglong2* fr = reinterpret_cast<const ulonglong2*>(sm + OFF_PRJ + win * 64);
            ull a0 = pack2(bias, 0.f), a1 = 0ull, a2 = 0ull, a3 = 0ull;
#pragma unroll
            for (int q = 0; q < 16; q++) {
                ulonglong2 fv = fr[q];
                if ((q & 1) == 0) { fma2(a0, wv[2 * q], fv.x); fma2(a1, wv[2 * q + 1], fv.y); }
                else              { fma2(a2, wv[2 * q], fv.x); fma2(a3, wv[2 * q + 1], fv.y); }
            }
            add2(a0, a0, a2);
            add2(a1, a1, a3);
            add2(a0, a0, a1);
            g_xg[(wbase + win) * NG + tid] = hsum2(a0);
        }
    }
}

// ---------------------------------------------------------------------------
// LSTM kernel: one block per batch row, 256 threads = one gate each.
// ---------------------------------------------------------------------------
__global__ void __launch_bounds__(256) lstm_kernel(
    const float* __restrict__ Whh, float* __restrict__ out) {
    __shared__ __align__(16) float s_h[PROJ];
    __shared__ float s_gact[NG];

    const int tid = threadIdx.x;
    const int b = blockIdx.x;
    const int cls = tid >> 6;  // 0:i 1:f 2:g 3:o

    ull wreg[PROJ / 2];
    {
        const ulonglong2* w2 = reinterpret_cast<const ulonglong2*>(Whh + tid * PROJ);
#pragma unroll
        for (int q = 0; q < PROJ / 4; q++) {
            ulonglong2 v = w2[q];
            wreg[2 * q] = v.x;
            wreg[2 * q + 1] = v.y;
        }
    }

    if (tid < PROJ) s_h[tid] = 0.f;
    float c = 0.f;

    const float* xg = g_xg + b * T * NG;
    float* hs = g_hs + b * T * PROJ;
    float xnext = xg[tid];
    __syncthreads();

    for (int t = 0; t < T; t++) {
        float xcur = xnext;
        int tn = (t + 1 < T) ? (t + 1) : (T - 1);
        xnext = xg[tn * NG + tid];

        ull a0 = pack2(xcur, 0.f), a1 = 0ull, a2 = 0ull, a3 = 0ull;
        const ulonglong2* h2 = reinterpret_cast<const ulonglong2*>(s_h);
#pragma unroll
        for (int q = 0; q < 16; q++) {
            ulonglong2 hv = h2[q];
            if ((q & 1) == 0) { fma2(a0, wreg[2 * q], hv.x); fma2(a1, wreg[2 * q + 1], hv.y); }
            else              { fma2(a2, wreg[2 * q], hv.x); fma2(a3, wreg[2 * q + 1], hv.y); }
        }
        add2(a0, a0, a2);
        add2(a1, a1, a3);
        add2(a0, a0, a1);
        float g = hsum2(a0);
        s_gact[tid] = (cls == 2) ? tanh_(g) : sigm(g);
        __syncthreads();

        if (tid < PROJ) {
            float ai = s_gact[tid];
            float af = s_gact[PROJ + tid];
            float ag = s_gact[2 * PROJ + tid];
            float ao = s_gact[3 * PROJ + tid];
            c = fmaf(af, c, ai * ag);
            float h = ao * tanh_(c);
            s_h[tid] = h;
            hs[t * PROJ + tid] = h;
        }
        __syncthreads();
    }

    if (tid < PROJ) {
        out[B * T * 4 + b * PROJ + tid] = s_h[tid];             // hT
        out[B * T * 4 + B * PROJ + b * PROJ + tid] = c;         // cT
    }
}

// ---------------------------------------------------------------------------
// Head kernel: out[wi, m] = sigmoid(h[wi] . hw[m] + hb[m]), fully parallel.
// ---------------------------------------------------------------------------
__global__ void __launch_bounds__(256) head_kernel(
    const float* __restrict__ hw, const float* __restrict__ hb,
    float* __restrict__ out) {
    __shared__ __align__(16) float s_hw[4 * PROJ];
    __shared__ float s_hb[4];
    const int tid = threadIdx.x;
    s_hw[tid] = hw[tid];
    if (tid < 4) s_hb[tid] = hb[tid];
    __syncthreads();

    const int gid = blockIdx.x * 256 + tid;
    const int wi = gid >> 2, m = gid & 3;
    const float4* hr = reinterpret_cast<const float4*>(g_hs + wi * PROJ);
    const float4* wr = reinterpret_cast<const float4*>(s_hw) + m * 16;
    float a0 = s_hb[m], a1 = 0.f;
#pragma unroll
    for (int q = 0; q < 16; q += 2) {
        float4 h0 = hr[q], w0 = wr[q];
        float4 h1 = hr[q + 1], w1 = wr[q + 1];
        a0 = fmaf(h0.x, w0.x, a0); a0 = fmaf(h0.y, w0.y, a0);
        a0 = fmaf(h0.z, w0.z, a0); a0 = fmaf(h0.w, w0.w, a0);
        a1 = fmaf(h1.x, w1.x, a1); a1 = fmaf(h1.y, w1.y, a1);
        a1 = fmaf(h1.z, w1.z, a1); a1 = fmaf(h1.w, w1.w, a1);
    }
    out[gid] = sigm(a0 + a1);
}

// ---------------------------------------------------------------------------
extern "C" void kernel_launch(void* const* d_in, const int* in_sizes, int n_in,
                              void* d_out, int out_size) {
    const float* pressure = (const float*)d_in[0];
    const float* torque   = (const float*)d_in[1];
    const float* frag     = (const float*)d_in[2];
    const float* pw1 = (const float*)d_in[3];
    const float* pb1 = (const float*)d_in[4];
    const float* pw2 = (const float*)d_in[5];
    const float* pb2 = (const float*)d_in[6];
    const float* tw1 = (const float*)d_in[7];
    const float* tb1 = (const float*)d_in[8];
    const float* tw2 = (const float*)d_in[9];
    const float* tb2 = (const float*)d_in[10];
    const float* fw  = (const float*)d_in[11];
    const float* fb  = (const float*)d_in[12];
    const float* prw = (const float*)d_in[13];
    const float* prb = (const float*)d_in[14];
    const float* Wih = (const float*)d_in[15];
    const float* Whh = (const float*)d_in[16];
    const float* bih = (const float*)d_in[17];
    const float* bhh = (const float*)d_in[18];
    const float* hw  = (const float*)d_in[19];
    const float* hb  = (const float*)d_in[20];

    static bool attr_set = false;
    if (!attr_set) {
        cudaFuncSetAttribute(enc_kernel, cudaFuncAttributeMaxDynamicSharedMemorySize,
                             SMEM_BYTES);
        attr_set = true;
    }

    enc_kernel<<<NWIN / 8, 256, SMEM_BYTES>>>(pressure, torque, frag,
                                              pw1, pb1, pw2, pb2, tw1, tb1, tw2, tb2,
                                              fw, fb, prw, prb, Wih, bih, bhh);
    lstm_kernel<<<B, 256>>>(Whh, (float*)d_out);
    head_kernel<<<(B * T * 4) / 256, 256>>>(hw, hb, (float*)d_out);
}

// round 6
// speedup vs baseline: 3.0176x; 1.0375x over previous
#include <cuda_runtime.h>

#define DEVINL __device__ __forceinline__
typedef unsigned long long ull;

constexpr int B = 64, T = 256, W = 20, NP = 6, NT = 12, CC = 32, FD = 8, PROJ = 64;
constexpr int NG = 4 * PROJ;            // 256 gates
constexpr int NWIN = B * T;             // 16384

// scratch
__device__ float g_xg[NWIN * NG];       // 16 MB: xg = feat @ Wih^T + (bih+bhh)
__device__ float g_hs[NWIN * PROJ];     // 4 MB: per-step hidden states

DEVINL void fma2(ull& d, ull a, ull b) {
    asm("fma.rn.f32x2 %0, %1, %2, %0;" : "+l"(d) : "l"(a), "l"(b));
}
DEVINL void add2(ull& d, ull a, ull b) {
    asm("add.rn.f32x2 %0, %1, %2;" : "=l"(d) : "l"(a), "l"(b));
}
DEVINL float hsum2(ull a) {
    float lo, hi;
    asm("mov.b64 {%0,%1}, %2;" : "=f"(lo), "=f"(hi) : "l"(a));
    return lo + hi;
}
DEVINL ull pack2(float lo, float hi) {
    ull r;
    asm("mov.b64 %0, {%1,%2};" : "=l"(r) : "f"(lo), "f"(hi));
    return r;
}

DEVINL float sigm(float x) { return __fdividef(1.f, 1.f + __expf(-x)); }
DEVINL float tanh_(float x) { return __fdividef(2.f, 1.f + __expf(-2.f * x)) - 1.f; }

// ---------------------------------------------------------------------------
// smem layout (floats) — dynamic shared
//   conv1p weights: channel-PAIRS  [(3m+k)*64 + 2o]   (stride 6 breaks quads)
//   conv1t / conv2 weights: channel-QUADS [(3mm+k)*128 + 4o]
// ---------------------------------------------------------------------------
constexpr int OFF_W1P  = 0;                       // 3m x 3k x 64 = 576
constexpr int OFF_W1T  = OFF_W1P + 576;           // 3mm x 3k x 128 = 1152
constexpr int OFF_W2P  = OFF_W1T + 1152;          // 8mm x 3k x 128 = 3072
constexpr int OFF_W2T  = OFF_W2P + 3072;          // 3072
constexpr int OFF_B1P  = OFF_W2T + 3072;          // 32
constexpr int OFF_B1T  = OFF_B1P + 32;            // 32
constexpr int OFF_B2P  = OFF_B1T + 32;            // 32
constexpr int OFF_B2T  = OFF_B2P + 32;            // 32
constexpr int OFF_BIAS = OFF_B2T + 32;            // 256
constexpr int OFF_XP   = OFF_BIAS + 256;          // 8 * 128  (x[l*6+i], raw layout)
constexpr int OFF_XT   = OFF_XP + 8 * 128;        // 8 * 256  (x[l*12+i])
constexpr int OFF_H1   = OFF_XT + 8 * 256;        // 8 * 576  (h1T[j*32+o])
constexpr int OFF_CAT  = OFF_H1 + 8 * 576;        // 8 * 80
constexpr int OFF_PRJ  = OFF_CAT + 8 * 80;        // 8 * 64
constexpr int SMEM_FLOATS = OFF_PRJ + 8 * 64;
constexpr int SMEM_BYTES = SMEM_FLOATS * 4;

// ---------------------------------------------------------------------------
// conv1 over channel PAIRS (pressure, stride 6).
// ---------------------------------------------------------------------------
template <int NPAIR, int STRIDE>
DEVINL void conv1P(const float* __restrict__ s_x, const float* __restrict__ s_w,
                   float bv, float* __restrict__ h1T) {
    ull acc[18];
#pragma unroll
    for (int j = 0; j < 18; j++) acc[j] = 0ull;
#pragma unroll
    for (int m = 0; m < NPAIR; m++) {
        ull w0 = *reinterpret_cast<const ull*>(s_w + (3 * m + 0) * 64);
        ull w1 = *reinterpret_cast<const ull*>(s_w + (3 * m + 1) * 64);
        ull w2 = *reinterpret_cast<const ull*>(s_w + (3 * m + 2) * 64);
#pragma unroll
        for (int j = 0; j < 20; j++) {
            ull v = *reinterpret_cast<const ull*>(s_x + j * STRIDE + 2 * m);
            if (j < 18) fma2(acc[j], v, w0);
            if (j >= 1 && j <= 18) fma2(acc[j - 1], v, w1);
            if (j >= 2) fma2(acc[j - 2], v, w2);
        }
    }
#pragma unroll
    for (int j = 0; j < 18; j++)
        h1T[j * 32] = fmaxf(hsum2(acc[j]) + bv, 0.f);
}

// ---------------------------------------------------------------------------
// conv1 over channel QUADS (torque, stride 12). LDS.128 per v and per w tap.
// ---------------------------------------------------------------------------
template <int NQUAD, int STRIDE>
DEVINL void conv1Q(const float* __restrict__ s_x, const float* __restrict__ s_w,
                   float bv, float* __restrict__ h1T) {
    ull acc[18];
#pragma unroll
    for (int j = 0; j < 18; j++) acc[j] = 0ull;
#pragma unroll
    for (int mm = 0; mm < NQUAD; mm++) {
        ulonglong2 w0 = *reinterpret_cast<const ulonglong2*>(s_w + (3 * mm + 0) * 128);
        ulonglong2 w1 = *reinterpret_cast<const ulonglong2*>(s_w + (3 * mm + 1) * 128);
        ulonglong2 w2 = *reinterpret_cast<const ulonglong2*>(s_w + (3 * mm + 2) * 128);
#pragma unroll
        for (int j = 0; j < 20; j++) {
            ulonglong2 v = *reinterpret_cast<const ulonglong2*>(s_x + j * STRIDE + 4 * mm);
            if (j < 18)            { fma2(acc[j], v.x, w0.x);     fma2(acc[j], v.y, w0.y); }
            if (j >= 1 && j <= 18) { fma2(acc[j - 1], v.x, w1.x); fma2(acc[j - 1], v.y, w1.y); }
            if (j >= 2)            { fma2(acc[j - 2], v.x, w2.x); fma2(acc[j - 2], v.y, w2.y); }
        }
    }
#pragma unroll
    for (int j = 0; j < 18; j++)
        h1T[j * 32] = fmaxf(hsum2(acc[j]) + bv, 0.f);
}

// ---------------------------------------------------------------------------
// conv2 over channel QUADS + relu + mean pool.
// ---------------------------------------------------------------------------
DEVINL float conv2Q(const float* __restrict__ h1T, const float* __restrict__ s_w,
                    float bv) {
    ull acc[16];
#pragma unroll
    for (int j = 0; j < 16; j++) acc[j] = 0ull;
#pragma unroll 2
    for (int mm = 0; mm < 8; mm++) {
        ulonglong2 w0 = *reinterpret_cast<const ulonglong2*>(s_w + (3 * mm + 0) * 128);
        ulonglong2 w1 = *reinterpret_cast<const ulonglong2*>(s_w + (3 * mm + 1) * 128);
        ulonglong2 w2 = *reinterpret_cast<const ulonglong2*>(s_w + (3 * mm + 2) * 128);
#pragma unroll
        for (int j = 0; j < 18; j++) {
            ulonglong2 v = *reinterpret_cast<const ulonglong2*>(h1T + j * 32 + 4 * mm);
            if (j < 16)            { fma2(acc[j], v.x, w0.x);     fma2(acc[j], v.y, w0.y); }
            if (j >= 1 && j <= 16) { fma2(acc[j - 1], v.x, w1.x); fma2(acc[j - 1], v.y, w1.y); }
            if (j >= 2)            { fma2(acc[j - 2], v.x, w2.x); fma2(acc[j - 2], v.y, w2.y); }
        }
    }
    float s = 0.f;
#pragma unroll
    for (int j = 0; j < 16; j++)
        s += fmaxf(hsum2(acc[j]) + bv, 0.f);
    return s * (1.f / 16.f);
}

// ---------------------------------------------------------------------------
// Encoder kernel: warp = one window.
// ---------------------------------------------------------------------------
__global__ void __launch_bounds__(256) enc_kernel(
    const float* __restrict__ pressure, const float* __restrict__ torque,
    const float* __restrict__ frag,
    const float* __restrict__ pw1, const float* __restrict__ pb1,
    const float* __restrict__ pw2, const float* __restrict__ pb2,
    const float* __restrict__ tw1, const float* __restrict__ tb1,
    const float* __restrict__ tw2, const float* __restrict__ tb2,
    const float* __restrict__ fw, const float* __restrict__ fb,
    const float* __restrict__ prw, const float* __restrict__ prb,
    const float* __restrict__ Wih, const float* __restrict__ bih,
    const float* __restrict__ bhh) {
    extern __shared__ float sm[];
    const int tid = threadIdx.x;
    const int lane = tid & 31;
    const int warp = tid >> 5;

    // ---- stage weights ----
    for (int t = tid; t < 32 * 3 * 3; t += 256) {         // conv1p pairs
        int o = t / 9, rem = t % 9, m = rem / 3, k = rem % 3;
        int di = OFF_W1P + (3 * m + k) * 64 + 2 * o;
        sm[di]     = pw1[(o * NP + 2 * m) * 3 + k];
        sm[di + 1] = pw1[(o * NP + 2 * m + 1) * 3 + k];
    }
    for (int t = tid; t < 32 * 3 * 3; t += 256) {         // conv1t quads: o x mm(3) x k(3)
        int o = t / 9, rem = t % 9, mm = rem / 3, k = rem % 3;
        int di = OFF_W1T + (3 * mm + k) * 128 + 4 * o;
#pragma unroll
        for (int q = 0; q < 4; q++)
            sm[di + q] = tw1[(o * NT + 4 * mm + q) * 3 + k];
    }
    for (int t = tid; t < 32 * 8 * 3; t += 256) {         // conv2 quads: o x mm(8) x k(3)
        int o = t / 24, rem = t % 24, mm = rem / 3, k = rem % 3;
        int di = (3 * mm + k) * 128 + 4 * o;
#pragma unroll
        for (int q = 0; q < 4; q++) {
            int si = (o * CC + 4 * mm + q) * 3 + k;
            sm[OFF_W2P + di + q] = pw2[si];
            sm[OFF_W2T + di + q] = tw2[si];
        }
    }
    if (tid < 32) {
        sm[OFF_B1P + tid] = pb1[tid]; sm[OFF_B1T + tid] = tb1[tid];
        sm[OFF_B2P + tid] = pb2[tid]; sm[OFF_B2T + tid] = tb2[tid];
    }
    sm[OFF_BIAS + tid] = bih[tid] + bhh[tid];
    __syncthreads();

    const int wi = blockIdx.x * 8 + warp;
    const int b = wi >> 8;

    float* sxp = sm + OFF_XP + warp * 128;
    float* sxt = sm + OFF_XT + warp * 256;
    float* sh1 = sm + OFF_H1 + warp * 576;
    float* sft = sm + OFF_CAT + warp * 80;
    float* spj = sm + OFF_PRJ + warp * 64;

    // ---- load window inputs (raw [pos][ch] layout kept) ----
    {
        const float4* gp4 = reinterpret_cast<const float4*>(pressure + wi * 120);
        if (lane < 30) reinterpret_cast<float4*>(sxp)[lane] = gp4[lane];
        const float4* gt4 = reinterpret_cast<const float4*>(torque + wi * 240);
        reinterpret_cast<float4*>(sxt)[lane] = gt4[lane];
        if (lane < 28) reinterpret_cast<float4*>(sxt)[lane + 32] = gt4[lane + 32];
    }
    __syncwarp();

    // ---- pressure: conv1 -> h1T -> conv2 -> pooled ----
    conv1P<3, NP>(sxp, sm + OFF_W1P + 2 * lane, sm[OFF_B1P + lane], sh1 + lane);
    __syncwarp();
    float poolp = conv2Q(sh1, sm + OFF_W2P + 4 * lane, sm[OFF_B2P + lane]);
    __syncwarp();

    // ---- torque: conv1 -> h1T -> conv2 -> pooled ----
    conv1Q<3, NT>(sxt, sm + OFF_W1T + 4 * lane, sm[OFF_B1T + lane], sh1 + lane);
    __syncwarp();
    float poolt = conv2Q(sh1, sm + OFF_W2T + 4 * lane, sm[OFF_B2T + lane]);

    sft[lane] = poolp;
    sft[32 + lane] = poolt;
    if (lane < FD) sft[64 + lane] = fmaxf(fmaf(frag[b], fw[lane], fb[lane]), 0.f);
    __syncwarp();

    // ---- projection: 2 outputs per lane, packed dot-72 ----
    {
        ull a0 = 0ull, a1 = 0ull, b0 = 0ull, b1 = 0ull;
        const ull* w0 = reinterpret_cast<const ull*>(prw + lane * 72);
        const ull* w1 = reinterpret_cast<const ull*>(prw + (lane + 32) * 72);
        const ull* cv = reinterpret_cast<const ull*>(sft);
#pragma unroll
        for (int q = 0; q < 36; q += 2) {
            ull x0 = cv[q], x1 = cv[q + 1];
            fma2(a0, w0[q], x0); fma2(b0, w0[q + 1], x1);
            fma2(a1, w1[q], x0); fma2(b1, w1[q + 1], x1);
        }
        add2(a0, a0, b0);
        add2(a1, a1, b1);
        spj[lane]      = fmaxf(hsum2(a0) + prb[lane], 0.f);
        spj[lane + 32] = fmaxf(hsum2(a1) + prb[lane + 32], 0.f);
    }
    __syncthreads();

    // ---- xg: gate tid for all 8 windows; Wih row held in registers ----
    {
        ull wv[32];
        const ulonglong2* wr = reinterpret_cast<const ulonglong2*>(Wih + tid * PROJ);
#pragma unroll
        for (int q = 0; q < 16; q++) {
            ulonglong2 v = wr[q];
            wv[2 * q] = v.x; wv[2 * q + 1] = v.y;
        }
        float bias = sm[OFF_BIAS + tid];
        const int wbase = blockIdx.x * 8;
#pragma unroll 2
        for (int win = 0; win < 8; win++) {
            const ulonglong2* fr = reinterpret_cast<const ulonglong2*>(sm + OFF_PRJ + win * 64);
            ull a0 = pack2(bias, 0.f), a1 = 0ull, a2 = 0ull, a3 = 0ull;
#pragma unroll
            for (int q = 0; q < 16; q++) {
                ulonglong2 fv = fr[q];
                if ((q & 1) == 0) { fma2(a0, wv[2 * q], fv.x); fma2(a1, wv[2 * q + 1], fv.y); }
                else              { fma2(a2, wv[2 * q], fv.x); fma2(a3, wv[2 * q + 1], fv.y); }
            }
            add2(a0, a0, a2);
            add2(a1, a1, a3);
            add2(a0, a0, a1);
            g_xg[(wbase + win) * NG + tid] = hsum2(a0);
        }
    }
}

// ---------------------------------------------------------------------------
// LSTM kernel: one block per batch row. Warp w covers hidden jj = w*8..w*8+7,
// lane = cls*8 + (jj&7). Gate exchange via 3x shfl_xor (no smem, no barrier);
// cell state replicated x4; ONE barrier per step, double-buffered h.
// ---------------------------------------------------------------------------
__global__ void __launch_bounds__(256) lstm_kernel(
    const float* __restrict__ Whh, float* __restrict__ out) {
    __shared__ __align__(16) float s_h[2][PROJ];

    const int tid = threadIdx.x;
    const int lane = tid & 31;
    const int w = tid >> 5;
    const int cls = lane >> 3;            // gate class 0:i 1:f 2:g 3:o
    const int jj = w * 8 + (lane & 7);    // hidden index 0..63
    const int row = cls * 64 + jj;        // gate row 0..255
    const int b = blockIdx.x;

    ull wreg[PROJ / 2];
    {
        const ulonglong2* w2 = reinterpret_cast<const ulonglong2*>(Whh + row * PROJ);
#pragma unroll
        for (int q = 0; q < PROJ / 4; q++) {
            ulonglong2 v = w2[q];
            wreg[2 * q] = v.x;
            wreg[2 * q + 1] = v.y;
        }
    }

    if (tid < PROJ) { s_h[0][tid] = 0.f; s_h[1][tid] = 0.f; }
    float c = 0.f, hlast = 0.f;

    const float* xg = g_xg + b * T * NG;
    float* hs = g_hs + b * T * PROJ;
    float xnext = xg[row];
    __syncthreads();

    int p = 0;
    for (int t = 0; t < T; t++) {
        float xcur = xnext;
        int tn = (t + 1 < T) ? (t + 1) : (T - 1);
        xnext = xg[tn * NG + row];

        // matvec: row . h  (packed f32x2, 4 accumulator chains)
        ull a0 = pack2(xcur, 0.f), a1 = 0ull, a2 = 0ull, a3 = 0ull;
        const ulonglong2* h2 = reinterpret_cast<const ulonglong2*>(s_h[p]);
#pragma unroll
        for (int q = 0; q < 16; q++) {
            ulonglong2 hv = h2[q];
            if ((q & 1) == 0) { fma2(a0, wreg[2 * q], hv.x); fma2(a1, wreg[2 * q + 1], hv.y); }
            else              { fma2(a2, wreg[2 * q], hv.x); fma2(a3, wreg[2 * q + 1], hv.y); }
        }
        add2(a0, a0, a2);
        add2(a1, a1, a3);
        add2(a0, a0, a1);
        float g = hsum2(a0);
        float act = (cls == 2) ? tanh_(g) : sigm(g);

        // gather the 4 class activations for this jj via butterfly shfl
        float s1 = __shfl_xor_sync(0xffffffffu, act, 8);
        float pA = (cls & 1) ? s1 : act;     // class (cls&2)+0
        float pB = (cls & 1) ? act : s1;     // class (cls&2)+1
        float qA = __shfl_xor_sync(0xffffffffu, pA, 16);
        float qB = __shfl_xor_sync(0xffffffffu, pB, 16);
        float ai = (cls & 2) ? qA : pA;
        float af = (cls & 2) ? qB : pB;
        float ag = (cls & 2) ? pA : qA;
        float ao = (cls & 2) ? pB : qB;

        // replicated cell update (bitwise identical across the 4 class lanes)
        c = fmaf(af, c, ai * ag);
        float h = ao * tanh_(c);
        hlast = h;

        if (cls == 0) {
            s_h[1 - p][jj] = h;
            hs[t * PROJ + jj] = h;
        }
        __syncthreads();
        p ^= 1;
    }

    if (cls == 0) {
        out[B * T * 4 + b * PROJ + jj] = hlast;          // hT
        out[B * T * 4 + B * PROJ + b * PROJ + jj] = c;   // cT
    }
}

// ---------------------------------------------------------------------------
// Head kernel: out[wi, m] = sigmoid(h[wi] . hw[m] + hb[m]), fully parallel.
// ---------------------------------------------------------------------------
__global__ void __launch_bounds__(256) head_kernel(
    const float* __restrict__ hw, const float* __restrict__ hb,
    float* __restrict__ out) {
    __shared__ __align__(16) float s_hw[4 * PROJ];
    __shared__ float s_hb[4];
    const int tid = threadIdx.x;
    s_hw[tid] = hw[tid];
    if (tid < 4) s_hb[tid] = hb[tid];
    __syncthreads();

    const int gid = blockIdx.x * 256 + tid;
    const int wi = gid >> 2, m = gid & 3;
    const float4* hr = reinterpret_cast<const float4*>(g_hs + wi * PROJ);
    const float4* wr = reinterpret_cast<const float4*>(s_hw) + m * 16;
    float a0 = s_hb[m], a1 = 0.f;
#pragma unroll
    for (int q = 0; q < 16; q += 2) {
        float4 h0 = hr[q], w0 = wr[q];
        float4 h1 = hr[q + 1], w1 = wr[q + 1];
        a0 = fmaf(h0.x, w0.x, a0); a0 = fmaf(h0.y, w0.y, a0);
        a0 = fmaf(h0.z, w0.z, a0); a0 = fmaf(h0.w, w0.w, a0);
        a1 = fmaf(h1.x, w1.x, a1); a1 = fmaf(h1.y, w1.y, a1);
        a1 = fmaf(h1.z, w1.z, a1); a1 = fmaf(h1.w, w1.w, a1);
    }
    out[gid] = sigm(a0 + a1);
}

// ---------------------------------------------------------------------------
extern "C" void kernel_launch(void* const* d_in, const int* in_sizes, int n_in,
                              void* d_out, int out_size) {
    const float* pressure = (const float*)d_in[0];
    const float* torque   = (const float*)d_in[1];
    const float* frag     = (const float*)d_in[2];
    const float* pw1 = (const float*)d_in[3];
    const float* pb1 = (const float*)d_in[4];
    const float* pw2 = (const float*)d_in[5];
    const float* pb2 = (const float*)d_in[6];
    const float* tw1 = (const float*)d_in[7];
    const float* tb1 = (const float*)d_in[8];
    const float* tw2 = (const float*)d_in[9];
    const float* tb2 = (const float*)d_in[10];
    const float* fw  = (const float*)d_in[11];
    const float* fb  = (const float*)d_in[12];
    const float* prw = (const float*)d_in[13];
    const float* prb = (const float*)d_in[14];
    const float* Wih = (const float*)d_in[15];
    const float* Whh = (const float*)d_in[16];
    const float* bih = (const float*)d_in[17];
    const float* bhh = (const float*)d_in[18];
    const float* hw  = (const float*)d_in[19];
    const float* hb  = (const float*)d_in[20];

    static bool attr_set = false;
    if (!attr_set) {
        cudaFuncSetAttribute(enc_kernel, cudaFuncAttributeMaxDynamicSharedMemorySize,
                             SMEM_BYTES);
        attr_set = true;
    }

    enc_kernel<<<NWIN / 8, 256, SMEM_BYTES>>>(pressure, torque, frag,
                                              pw1, pb1, pw2, pb2, tw1, tb1, tw2, tb2,
                                              fw, fb, prw, prb, Wih, bih, bhh);
    lstm_kernel<<<B, 256>>>(Whh, (float*)d_out);
    head_kernel<<<(B * T * 4) / 256, 256>>>(hw, hb, (float*)d_out);
}